// round 1
// baseline (speedup 1.0000x reference)
#include <cuda_runtime.h>
#include <cstddef>

// ---------------------------------------------------------------------------
// Problem constants
// ---------------------------------------------------------------------------
#define NPOS   32768          // B*H*W*D = 1*32*32*32
#define CMODEL 128
#define DIN    256
#define NSTATE 16
#define DTRANK 8
#define LSEQ   32

// Scratch (device globals; no allocation allowed)
__device__ float g_xz[(size_t)NPOS * 512];   // in-projection output (xi | z), reused per branch
__device__ float g_y [(size_t)NPOS * 768];   // pre-out-proj y for all 3 branches, concatenated
__device__ float g_M [128 * 768];            // folded (outW_t -> fcW) matrix, row-major (128, 768)

// ---------------------------------------------------------------------------
// Fold outW_t and fcW into one matrix:
//   M[c2][t*256 + j] = sum_c fcW[c2][t*128 + c] * outW_t[c][j]
// ---------------------------------------------------------------------------
__global__ void build_M_kernel(const float* __restrict__ fcW,
                               const float* __restrict__ outW_v,
                               const float* __restrict__ outW_h,
                               const float* __restrict__ outW_d) {
    int idx = blockIdx.x * 256 + threadIdx.x;      // 0 .. 128*768-1
    if (idx >= 128 * 768) return;
    int c2 = idx / 768;
    int tj = idx - c2 * 768;
    int t  = tj >> 8;          // 0..2
    int j  = tj & 255;
    const float* oW = (t == 0) ? outW_v : (t == 1) ? outW_h : outW_d;
    const float* fr = fcW + c2 * 384 + t * 128;
    float acc = 0.f;
    #pragma unroll 8
    for (int c = 0; c < 128; c++)
        acc += fr[c] * oW[c * 256 + j];
    g_M[idx] = acc;
}

// ---------------------------------------------------------------------------
// SGEMM: C[M,N] = A[M,K] @ B[N,K]^T  (+ bias over N, optional)
// BM = BN = 64, BK = 16, 256 threads, 4x4 per thread. M%64==0, N%64==0, K%16==0.
// ---------------------------------------------------------------------------
__global__ void sgemm_tn_kernel(const float* __restrict__ A,
                                const float* __restrict__ B,
                                const float* __restrict__ bias,
                                float* __restrict__ C,
                                int M, int N, int K) {
    __shared__ float As[16][68];
    __shared__ float Bs[16][68];

    const int tid = threadIdx.x;
    const int tx = tid & 15;          // 0..15 -> N dim
    const int ty = tid >> 4;          // 0..15 -> M dim
    const int bm = blockIdx.y * 64;
    const int bn = blockIdx.x * 64;

    const int lr = tid >> 2;          // 0..63 tile row for loading
    const int lk = (tid & 3) * 4;     // 0,4,8,12 k offset

    const float* Ap = A + (size_t)(bm + lr) * K + lk;
    const float* Bp = B + (size_t)(bn + lr) * K + lk;

    float acc[4][4];
    #pragma unroll
    for (int i = 0; i < 4; i++)
        #pragma unroll
        for (int j = 0; j < 4; j++) acc[i][j] = 0.f;

    for (int k0 = 0; k0 < K; k0 += 16) {
        float4 av = *(const float4*)(Ap + k0);
        float4 bv = *(const float4*)(Bp + k0);
        As[lk + 0][lr] = av.x; As[lk + 1][lr] = av.y;
        As[lk + 2][lr] = av.z; As[lk + 3][lr] = av.w;
        Bs[lk + 0][lr] = bv.x; Bs[lk + 1][lr] = bv.y;
        Bs[lk + 2][lr] = bv.z; Bs[lk + 3][lr] = bv.w;
        __syncthreads();

        #pragma unroll
        for (int k = 0; k < 16; k++) {
            float4 a = *(const float4*)&As[k][ty * 4];
            float4 b = *(const float4*)&Bs[k][tx * 4];
            acc[0][0] += a.x * b.x; acc[0][1] += a.x * b.y;
            acc[0][2] += a.x * b.z; acc[0][3] += a.x * b.w;
            acc[1][0] += a.y * b.x; acc[1][1] += a.y * b.y;
            acc[1][2] += a.y * b.z; acc[1][3] += a.y * b.w;
            acc[2][0] += a.z * b.x; acc[2][1] += a.z * b.y;
            acc[2][2] += a.z * b.z; acc[2][3] += a.z * b.w;
            acc[3][0] += a.w * b.x; acc[3][1] += a.w * b.y;
            acc[3][2] += a.w * b.z; acc[3][3] += a.w * b.w;
        }
        __syncthreads();
    }

    float bval[4] = {0.f, 0.f, 0.f, 0.f};
    if (bias) {
        #pragma unroll
        for (int j = 0; j < 4; j++) bval[j] = bias[bn + tx * 4 + j];
    }
    #pragma unroll
    for (int i = 0; i < 4; i++) {
        int row = bm + ty * 4 + i;
        float4 r;
        r.x = acc[i][0] + bval[0];
        r.y = acc[i][1] + bval[1];
        r.z = acc[i][2] + bval[2];
        r.w = acc[i][3] + bval[3];
        *(float4*)(C + (size_t)row * N + bn + tx * 4) = r;
    }
}

// ---------------------------------------------------------------------------
// Fused depthwise-conv + SiLU + x-proj + dt-proj + selective scan + gating.
// One CTA per sequence (1024 CTAs), 256 threads = one per d_inner channel.
// Reads g_xz, writes g_y[:, branch*256 : branch*256+256].
// pos(l) = (blk>>5)*sHi + (blk&31)*sLo + l*sL   (original spatial flat index)
// ---------------------------------------------------------------------------
__device__ __forceinline__ float silu_f(float x) {
    return x / (1.f + expf(-x));
}

__global__ void __launch_bounds__(256)
mamba_scan_kernel(const float* __restrict__ convw,  // (256,4)
                  const float* __restrict__ convb,  // (256)
                  const float* __restrict__ xpW,    // (40,256)
                  const float* __restrict__ dtW,    // (256,8)
                  const float* __restrict__ dtb,    // (256)
                  const float* __restrict__ Alog,   // (256,16)
                  const float* __restrict__ Dp,     // (256)
                  int sHi, int sLo, int sL, int branch) {
    __shared__ float xc_s[LSEQ][DIN];        // 32 KB
    __shared__ float dbc_s[LSEQ][40];        // 5 KB
    __shared__ float xpw_s[40][65];          // 10.2 KB (chunked staging, padded)

    const int i   = threadIdx.x;             // channel
    const int blk = blockIdx.x;
    const int base = (blk >> 5) * sHi + (blk & 31) * sLo;

    // ---- Phase 1: depthwise causal conv (width 4) + SiLU -> xc_s ----
    {
        const float cw0 = convw[i * 4 + 0];
        const float cw1 = convw[i * 4 + 1];
        const float cw2 = convw[i * 4 + 2];
        const float cw3 = convw[i * 4 + 3];
        const float cb  = convb[i];
        float w0 = 0.f, w1 = 0.f, w2 = 0.f;
        #pragma unroll
        for (int l = 0; l < LSEQ; l++) {
            float cur = g_xz[(size_t)(base + l * sL) * 512 + i];
            float v = cb + cw0 * w0 + cw1 * w1 + cw2 * w2 + cw3 * cur;
            xc_s[l][i] = silu_f(v);
            w0 = w1; w1 = w2; w2 = cur;
        }
    }
    __syncthreads();

    // ---- Phase 2: dbc[l][j] = xc_s[l][:] . xpW[j][:]  (1280 dots, 5/thread) ----
    {
        float acc5[5] = {0.f, 0.f, 0.f, 0.f, 0.f};
        int l5[5], j5[5];
        #pragma unroll
        for (int p5 = 0; p5 < 5; p5++) {
            int p = i + p5 * 256;
            l5[p5] = p / 40;
            j5[p5] = p - l5[p5] * 40;
        }
        for (int c = 0; c < 4; c++) {            // K chunks of 64
            for (int e = i; e < 40 * 64; e += 256) {
                int j  = e >> 6;
                int ii = e & 63;
                xpw_s[j][ii] = xpW[j * 256 + c * 64 + ii];
            }
            __syncthreads();
            #pragma unroll
            for (int p5 = 0; p5 < 5; p5++) {
                const float* xr = &xc_s[l5[p5]][c * 64];
                const float* wr = &xpw_s[j5[p5]][0];
                float a = acc5[p5];
                #pragma unroll 16
                for (int ii = 0; ii < 64; ii++) a += xr[ii] * wr[ii];
                acc5[p5] = a;
            }
            __syncthreads();
        }
        #pragma unroll
        for (int p5 = 0; p5 < 5; p5++)
            dbc_s[l5[p5]][j5[p5]] = acc5[p5];
    }
    __syncthreads();

    // ---- Phase 3: dt softplus + selective scan + gating ----
    {
        float Areg[NSTATE];
        #pragma unroll
        for (int n = 0; n < NSTATE; n++)
            Areg[n] = -expf(Alog[i * NSTATE + n]);
        float dtw[DTRANK];
        #pragma unroll
        for (int r = 0; r < DTRANK; r++) dtw[r] = dtW[i * DTRANK + r];
        const float dtbi = dtb[i];
        const float dpi  = Dp[i];

        float h[NSTATE];
        #pragma unroll
        for (int n = 0; n < NSTATE; n++) h[n] = 0.f;

        for (int l = 0; l < LSEQ; l++) {
            const size_t pos = (size_t)(base + l * sL);
            float dtv = dtbi;
            #pragma unroll
            for (int r = 0; r < DTRANK; r++) dtv += dbc_s[l][r] * dtw[r];
            // softplus
            dtv = (dtv > 20.f) ? dtv : log1pf(expf(dtv));

            const float u  = xc_s[l][i];
            const float du = dtv * u;
            float y = 0.f;
            #pragma unroll
            for (int n = 0; n < NSTATE; n++) {
                float dA = expf(dtv * Areg[n]);
                h[n] = dA * h[n] + du * dbc_s[l][DTRANK + n];
                y += h[n] * dbc_s[l][DTRANK + NSTATE + n];
            }
            const float z  = g_xz[pos * 512 + 256 + i];
            const float yo = (y + u * dpi) * silu_f(z);
            g_y[pos * 768 + branch * 256 + i] = yo;
        }
    }
}

// ---------------------------------------------------------------------------
// Host launcher
// ---------------------------------------------------------------------------
extern "C" void kernel_launch(void* const* d_in, const int* in_sizes, int n_in,
                              void* d_out, int out_size) {
    (void)in_sizes; (void)n_in; (void)out_size;

    const float* x   = (const float*)d_in[0];
    // per-branch params: inW, convw, convb, xpW, dtW, dtb, Alog, Dp, outW
    const float* prm[3][9];
    for (int t = 0; t < 3; t++)
        for (int k = 0; k < 9; k++)
            prm[t][k] = (const float*)d_in[1 + t * 9 + k];
    const float* fcW = (const float*)d_in[28];
    const float* fcb = (const float*)d_in[29];
    float* out = (float*)d_out;

    float *xz, *ybuf, *Mmat;
    cudaGetSymbolAddress((void**)&xz,   g_xz);
    cudaGetSymbolAddress((void**)&ybuf, g_y);
    cudaGetSymbolAddress((void**)&Mmat, g_M);

    // Fold outW_t + fcW
    build_M_kernel<<<(128 * 768 + 255) / 256, 256>>>(fcW, prm[0][8], prm[1][8], prm[2][8]);

    // Per-branch sequence strides:  pos = (blk>>5)*sHi + (blk&31)*sLo + l*sL
    const int sHi[3] = {  32, 1024, 1024};
    const int sLo[3] = {   1,    1,   32};
    const int sL [3] = {1024,   32,    1};

    dim3 g1(512 / 64, NPOS / 64);   // in-proj GEMM grid (N=512)
    for (int t = 0; t < 3; t++) {
        // xz = x @ inW_t^T   (32768,128)x(512,128)^T
        sgemm_tn_kernel<<<g1, 256>>>(x, prm[t][0], nullptr, xz, NPOS, 512, CMODEL);
        // fused conv + scan
        mamba_scan_kernel<<<1024, 256>>>(prm[t][1], prm[t][2], prm[t][3], prm[t][4],
                                         prm[t][5], prm[t][6], prm[t][7],
                                         sHi[t], sLo[t], sL[t], t);
    }

    // out = ybuf(32768,768) @ M(128,768)^T + fcb
    dim3 g2(128 / 64, NPOS / 64);
    sgemm_tn_kernel<<<g2, 256>>>(ybuf, Mmat, fcb, out, NPOS, 128, 768);
}

// round 2
// speedup vs baseline: 1.0424x; 1.0424x over previous
#include <cuda_runtime.h>
#include <cstddef>

// ---------------------------------------------------------------------------
// Problem constants
// ---------------------------------------------------------------------------
#define NPOS   32768          // B*H*W*D = 1*32*32*32
#define CMODEL 128
#define DIN    256
#define NSTATE 16
#define DTRANK 8
#define LSEQ   32

// Scratch (device globals; no allocation allowed)
__device__ float g_xz[(size_t)NPOS * 512];   // in-projection output (xi | z)
__device__ float g_y [(size_t)NPOS * 768];   // pre-out-proj y, all 3 branches
__device__ float g_M [128 * 768];            // folded (outW_t -> fcW), row-major (128,768)

// ---------------------------------------------------------------------------
// Fold outW_t and fcW into one matrix:
//   M[c2][t*256 + j] = sum_c fcW[c2][t*128 + c] * outW_t[c][j]
// ---------------------------------------------------------------------------
__global__ void build_M_kernel(const float* __restrict__ fcW,
                               const float* __restrict__ outW_v,
                               const float* __restrict__ outW_h,
                               const float* __restrict__ outW_d) {
    int idx = blockIdx.x * 256 + threadIdx.x;      // 0 .. 128*768-1
    if (idx >= 128 * 768) return;
    int c2 = idx / 768;
    int tj = idx - c2 * 768;
    int t  = tj >> 8;          // 0..2
    int j  = tj & 255;
    const float* oW = (t == 0) ? outW_v : (t == 1) ? outW_h : outW_d;
    const float* fr = fcW + c2 * 384 + t * 128;
    float acc = 0.f;
    #pragma unroll 8
    for (int c = 0; c < 128; c++)
        acc += fr[c] * oW[c * 256 + j];
    g_M[idx] = acc;
}

// ---------------------------------------------------------------------------
// SGEMM: C[M,N] = A[M,K] @ B[N,K]^T (+bias over N, optional)
// BM = BN = 128, BK = 16, 256 threads, 8x8 per thread, reg-prefetched loads.
// Requires M%128==0, N%128==0, K%16==0.
// ---------------------------------------------------------------------------
__global__ void __launch_bounds__(256, 2)
sgemm_tn128(const float* __restrict__ A,
            const float* __restrict__ B,
            const float* __restrict__ bias,
            float* __restrict__ C,
            int M, int N, int K) {
    __shared__ float As[16][132];
    __shared__ float Bs[16][132];

    const int tid = threadIdx.x;
    const int tx = tid & 15;          // 0..15 -> N dim (8 cols each)
    const int ty = tid >> 4;          // 0..15 -> M dim (8 rows each)
    const int bm = blockIdx.y * 128;
    const int bn = blockIdx.x * 128;

    const int lr = tid & 127;         // tile row for loading (0..127)
    const int lk = (tid >> 7) * 8;    // 0 or 8 (k offset)

    const float* Ap = A + (size_t)(bm + lr) * K + lk;
    const float* Bp = B + (size_t)(bn + lr) * K + lk;

    // prefetch first tile into registers
    float4 a0v = *(const float4*)(Ap);
    float4 a1v = *(const float4*)(Ap + 4);
    float4 b0v = *(const float4*)(Bp);
    float4 b1v = *(const float4*)(Bp + 4);

    float acc[8][8];
    #pragma unroll
    for (int i = 0; i < 8; i++)
        #pragma unroll
        for (int j = 0; j < 8; j++) acc[i][j] = 0.f;

    for (int k0 = 0; k0 < K; k0 += 16) {
        // commit staged registers to smem
        As[lk + 0][lr] = a0v.x; As[lk + 1][lr] = a0v.y;
        As[lk + 2][lr] = a0v.z; As[lk + 3][lr] = a0v.w;
        As[lk + 4][lr] = a1v.x; As[lk + 5][lr] = a1v.y;
        As[lk + 6][lr] = a1v.z; As[lk + 7][lr] = a1v.w;
        Bs[lk + 0][lr] = b0v.x; Bs[lk + 1][lr] = b0v.y;
        Bs[lk + 2][lr] = b0v.z; Bs[lk + 3][lr] = b0v.w;
        Bs[lk + 4][lr] = b1v.x; Bs[lk + 5][lr] = b1v.y;
        Bs[lk + 6][lr] = b1v.z; Bs[lk + 7][lr] = b1v.w;
        __syncthreads();

        // prefetch next tile
        if (k0 + 16 < K) {
            a0v = *(const float4*)(Ap + k0 + 16);
            a1v = *(const float4*)(Ap + k0 + 20);
            b0v = *(const float4*)(Bp + k0 + 16);
            b1v = *(const float4*)(Bp + k0 + 20);
        }

        #pragma unroll
        for (int k = 0; k < 16; k++) {
            float4 a0 = *(const float4*)&As[k][ty * 8];
            float4 a1 = *(const float4*)&As[k][ty * 8 + 4];
            float4 b0 = *(const float4*)&Bs[k][tx * 8];
            float4 b1 = *(const float4*)&Bs[k][tx * 8 + 4];
            float am[8] = {a0.x, a0.y, a0.z, a0.w, a1.x, a1.y, a1.z, a1.w};
            float bn_[8] = {b0.x, b0.y, b0.z, b0.w, b1.x, b1.y, b1.z, b1.w};
            #pragma unroll
            for (int i = 0; i < 8; i++)
                #pragma unroll
                for (int j = 0; j < 8; j++)
                    acc[i][j] += am[i] * bn_[j];
        }
        __syncthreads();
    }

    float bval[8];
    #pragma unroll
    for (int j = 0; j < 8; j++)
        bval[j] = bias ? bias[bn + tx * 8 + j] : 0.f;

    #pragma unroll
    for (int i = 0; i < 8; i++) {
        int row = bm + ty * 8 + i;
        float4 r0, r1;
        r0.x = acc[i][0] + bval[0]; r0.y = acc[i][1] + bval[1];
        r0.z = acc[i][2] + bval[2]; r0.w = acc[i][3] + bval[3];
        r1.x = acc[i][4] + bval[4]; r1.y = acc[i][5] + bval[5];
        r1.z = acc[i][6] + bval[6]; r1.w = acc[i][7] + bval[7];
        float* cp = C + (size_t)row * N + bn + tx * 8;
        *(float4*)(cp)     = r0;
        *(float4*)(cp + 4) = r1;
    }
}

// ---------------------------------------------------------------------------
// Fused depthwise-conv + SiLU + x-proj + dt-proj + selective scan + gating.
// One CTA per sequence (1024 CTAs), 256 threads = one per d_inner channel.
// pos(l) = (blk>>5)*sHi + (blk&31)*sLo + l*sL
// ---------------------------------------------------------------------------
__device__ __forceinline__ float silu_f(float x) {
    return x / (1.f + __expf(-x));
}

__global__ void __launch_bounds__(256)
mamba_scan_kernel(const float* __restrict__ convw,  // (256,4)
                  const float* __restrict__ convb,  // (256)
                  const float* __restrict__ xpW,    // (40,256)
                  const float* __restrict__ dtW,    // (256,8)
                  const float* __restrict__ dtb,    // (256)
                  const float* __restrict__ Alog,   // (256,16)
                  const float* __restrict__ Dp,     // (256)
                  int sHi, int sLo, int sL, int branch) {
    __shared__ float xc_s[LSEQ][DIN];        // 32 KB
    __shared__ float dbc_s[LSEQ][40];        // 5 KB
    __shared__ float xpw_s[40][68];          // 10.6 KB (chunked staging, f4-aligned pad)

    const int i   = threadIdx.x;             // channel
    const int blk = blockIdx.x;
    const int base = (blk >> 5) * sHi + (blk & 31) * sLo;

    // ---- Phase 1: depthwise causal conv (width 4) + SiLU -> xc_s ----
    {
        const float cw0 = convw[i * 4 + 0];
        const float cw1 = convw[i * 4 + 1];
        const float cw2 = convw[i * 4 + 2];
        const float cw3 = convw[i * 4 + 3];
        const float cb  = convb[i];
        float w0 = 0.f, w1 = 0.f, w2 = 0.f;
        #pragma unroll
        for (int l = 0; l < LSEQ; l++) {
            float cur = g_xz[(size_t)(base + l * sL) * 512 + i];
            float v = cb + cw0 * w0 + cw1 * w1 + cw2 * w2 + cw3 * cur;
            xc_s[l][i] = silu_f(v);
            w0 = w1; w1 = w2; w2 = cur;
        }
    }
    __syncthreads();

    // ---- Phase 2: dbc[l][j] = xc_s[l][:] . xpW[j][:]
    //      thread -> (l = i>>3, j = (i&7)*5 + p5), shares xc operand across 5 j's
    {
        const int l2 = i >> 3;     // 0..31
        const int jg = i & 7;      // 0..7 -> j base jg*5
        float acc5[5] = {0.f, 0.f, 0.f, 0.f, 0.f};

        for (int c = 0; c < 4; c++) {            // K chunks of 64
            for (int e = i; e < 40 * 64; e += 256) {
                int j  = e >> 6;
                int ii = e & 63;
                xpw_s[j][ii] = xpW[j * 256 + c * 64 + ii];
            }
            __syncthreads();
            const float* xr = &xc_s[l2][c * 64];
            #pragma unroll 4
            for (int ii = 0; ii < 64; ii += 4) {
                float4 xv = *(const float4*)(xr + ii);
                #pragma unroll
                for (int p5 = 0; p5 < 5; p5++) {
                    float4 wv = *(const float4*)&xpw_s[jg * 5 + p5][ii];
                    acc5[p5] += xv.x * wv.x + xv.y * wv.y + xv.z * wv.z + xv.w * wv.w;
                }
            }
            __syncthreads();
        }
        #pragma unroll
        for (int p5 = 0; p5 < 5; p5++)
            dbc_s[l2][jg * 5 + p5] = acc5[p5];
    }
    __syncthreads();

    // ---- Phase 3: dt softplus + selective scan + gating ----
    {
        float Areg[NSTATE];
        #pragma unroll
        for (int n = 0; n < NSTATE; n++)
            Areg[n] = -expf(Alog[i * NSTATE + n]);

        // Structural check: is A_n == (n+1)*A_0 (standard Mamba init)?
        // If so one exp per step suffices (power chain).
        bool geom = true;
        #pragma unroll
        for (int n = 0; n < NSTATE; n++)
            geom = geom && (fabsf(Areg[n] - (float)(n + 1) * Areg[0])
                            <= 1e-5f * fabsf(Areg[n]));

        float dtw[DTRANK];
        #pragma unroll
        for (int r = 0; r < DTRANK; r++) dtw[r] = dtW[i * DTRANK + r];
        const float dtbi = dtb[i];
        const float dpi  = Dp[i];

        float h[NSTATE];
        #pragma unroll
        for (int n = 0; n < NSTATE; n++) h[n] = 0.f;

        for (int l = 0; l < LSEQ; l++) {
            const size_t pos = (size_t)(base + l * sL);
            float dtv = dtbi;
            #pragma unroll
            for (int r = 0; r < DTRANK; r++) dtv += dbc_s[l][r] * dtw[r];
            // softplus
            dtv = (dtv > 20.f) ? dtv : __logf(1.f + __expf(dtv));

            const float u  = xc_s[l][i];
            const float du = dtv * u;
            float y = 0.f;
            if (geom) {
                const float e1 = __expf(dtv * Areg[0]);
                float p = 1.f;
                #pragma unroll
                for (int n = 0; n < NSTATE; n++) {
                    p *= e1;                                     // e1^(n+1)
                    h[n] = p * h[n] + du * dbc_s[l][DTRANK + n];
                    y += h[n] * dbc_s[l][DTRANK + NSTATE + n];
                }
            } else {
                #pragma unroll
                for (int n = 0; n < NSTATE; n++) {
                    float dA = __expf(dtv * Areg[n]);
                    h[n] = dA * h[n] + du * dbc_s[l][DTRANK + n];
                    y += h[n] * dbc_s[l][DTRANK + NSTATE + n];
                }
            }
            const float z  = g_xz[pos * 512 + 256 + i];
            const float yo = (y + u * dpi) * silu_f(z);
            g_y[pos * 768 + branch * 256 + i] = yo;
        }
    }
}

// ---------------------------------------------------------------------------
// Host launcher
// ---------------------------------------------------------------------------
extern "C" void kernel_launch(void* const* d_in, const int* in_sizes, int n_in,
                              void* d_out, int out_size) {
    (void)in_sizes; (void)n_in; (void)out_size;

    const float* x   = (const float*)d_in[0];
    const float* prm[3][9];
    for (int t = 0; t < 3; t++)
        for (int k = 0; k < 9; k++)
            prm[t][k] = (const float*)d_in[1 + t * 9 + k];
    const float* fcW = (const float*)d_in[28];
    const float* fcb = (const float*)d_in[29];
    float* out = (float*)d_out;

    float *xz, *ybuf, *Mmat;
    cudaGetSymbolAddress((void**)&xz,   g_xz);
    cudaGetSymbolAddress((void**)&ybuf, g_y);
    cudaGetSymbolAddress((void**)&Mmat, g_M);

    // Fold outW_t + fcW
    build_M_kernel<<<(128 * 768 + 255) / 256, 256>>>(fcW, prm[0][8], prm[1][8], prm[2][8]);

    // Per-branch sequence strides:  pos = (blk>>5)*sHi + (blk&31)*sLo + l*sL
    const int sHi[3] = {  32, 1024, 1024};
    const int sLo[3] = {   1,    1,   32};
    const int sL [3] = {1024,   32,    1};

    dim3 g1(512 / 128, NPOS / 128);   // in-proj GEMM grid (N=512)
    for (int t = 0; t < 3; t++) {
        // xz = x @ inW_t^T   (32768,128)x(512,128)^T
        sgemm_tn128<<<g1, 256>>>(x, prm[t][0], nullptr, xz, NPOS, 512, CMODEL);
        // fused conv + scan
        mamba_scan_kernel<<<1024, 256>>>(prm[t][1], prm[t][2], prm[t][3], prm[t][4],
                                         prm[t][5], prm[t][6], prm[t][7],
                                         sHi[t], sLo[t], sL[t], t);
    }

    // out = ybuf(32768,768) @ M(128,768)^T + fcb
    dim3 g2(1, NPOS / 128);
    sgemm_tn128<<<g2, 256>>>(ybuf, Mmat, fcb, out, NPOS, 128, 768);
}

// round 6
// speedup vs baseline: 1.8695x; 1.7935x over previous
#include <cuda_runtime.h>
#include <cuda_fp16.h>
#include <mma.h>
#include <cstdint>
#include <cstddef>

using namespace nvcuda;

// ---------------------------------------------------------------------------
// Problem constants
// ---------------------------------------------------------------------------
#define NPOS   32768          // B*H*W*D = 1*32*32*32
#define CMODEL 128
#define DIN    256
#define NSTATE 16
#define DTRANK 8
#define LSEQ   32

// Scratch (device globals; no allocation allowed)
__device__ __half g_xh [(size_t)NPOS * 128];   // x in fp16 (in-proj A operand)
__device__ __half g_wh [3 * 512 * 128];        // inW per branch, fp16 (N=512, K=128)
__device__ float  g_xz [(size_t)NPOS * 512];   // in-projection output (xi | z), fp32
__device__ __half g_yh [(size_t)NPOS * 768];   // pre-out-proj y (3 branches), fp16
__device__ __half g_Mh [128 * 768];            // folded (outW_t -> fcW), fp16 (N=128,K=768)

// ===========================================================================
// WMMA fp16 GEMM: C[M,N](fp32) = A[M,K](fp16) @ B[N,K](fp16)^T
// BM=BN=128, BK=64, 256 threads (8 warps, each 64x32).
// Requires M%128==0, N%128==0, K%64==0.
// ===========================================================================
__global__ void __launch_bounds__(256)
hgemm_wmma(const __half* __restrict__ A, const __half* __restrict__ B,
           float* __restrict__ C, int M, int N, int K) {
    __shared__ __half As[128][72];     // 64 + 8 pad
    __shared__ __half Bs[128][72];

    const int tid = threadIdx.x;
    const int wid = tid >> 5;
    const int warp_m = wid & 1;        // 0..1 -> 64-row slab
    const int warp_n = wid >> 1;       // 0..3 -> 32-col slab
    const int bm = blockIdx.y * 128;
    const int bn = blockIdx.x * 128;

    wmma::fragment<wmma::accumulator, 16, 16, 16, float> acc[4][2];
    #pragma unroll
    for (int i = 0; i < 4; i++)
        #pragma unroll
        for (int j = 0; j < 2; j++)
            wmma::fill_fragment(acc[i][j], 0.f);

    const int krow4 = K >> 3;          // uint4 per global row

    for (int k0 = 0; k0 < K; k0 += 64) {
        // Load A and B tiles: 128 rows x 64 halves each = 1024 uint4 each
        #pragma unroll
        for (int it = 0; it < 4; it++) {
            int idx = tid + it * 256;          // 0..1023
            int r = idx >> 3, c8 = idx & 7;    // row, 8-half group
            const uint4* Ag = (const uint4*)(A + (size_t)(bm + r) * K + k0);
            *(uint4*)&As[r][c8 * 8] = Ag[c8];
            const uint4* Bg = (const uint4*)(B + (size_t)(bn + r) * K + k0);
            *(uint4*)&Bs[r][c8 * 8] = Bg[c8];
        }
        __syncthreads();

        #pragma unroll
        for (int kk = 0; kk < 64; kk += 16) {
            wmma::fragment<wmma::matrix_a, 16, 16, 16, __half, wmma::row_major> af[4];
            wmma::fragment<wmma::matrix_b, 16, 16, 16, __half, wmma::col_major> bf[2];
            #pragma unroll
            for (int i = 0; i < 4; i++)
                wmma::load_matrix_sync(af[i], &As[warp_m * 64 + i * 16][kk], 72);
            #pragma unroll
            for (int j = 0; j < 2; j++)
                wmma::load_matrix_sync(bf[j], &Bs[warp_n * 32 + j * 16][kk], 72);
            #pragma unroll
            for (int i = 0; i < 4; i++)
                #pragma unroll
                for (int j = 0; j < 2; j++)
                    wmma::mma_sync(acc[i][j], af[i], bf[j], acc[i][j]);
        }
        __syncthreads();
    }

    #pragma unroll
    for (int i = 0; i < 4; i++)
        #pragma unroll
        for (int j = 0; j < 2; j++) {
            int row = bm + warp_m * 64 + i * 16;
            int col = bn + warp_n * 32 + j * 16;
            wmma::store_matrix_sync(C + (size_t)row * N + col, acc[i][j], N,
                                    wmma::mem_row_major);
        }
}

// ---------------------------------------------------------------------------
// Conversion / epilogue kernels
// ---------------------------------------------------------------------------
__global__ void cvt_x_kernel(const float* __restrict__ x, __half* __restrict__ xh) {
    int idx = blockIdx.x * 256 + threadIdx.x;       // float4 index, total 1M
    float4 v = ((const float4*)x)[idx];
    __half2 a = __floats2half2_rn(v.x, v.y);
    __half2 b = __floats2half2_rn(v.z, v.w);
    uint2 o;
    o.x = *(uint32_t*)&a;
    o.y = *(uint32_t*)&b;
    ((uint2*)xh)[idx] = o;
}

__global__ void cvt_w_kernel(const float* __restrict__ w0, const float* __restrict__ w1,
                             const float* __restrict__ w2) {
    int idx = blockIdx.x * 256 + threadIdx.x;       // 0 .. 3*65536-1
    int t = idx >> 16;
    int e = idx & 65535;
    const float* w = (t == 0) ? w0 : (t == 1) ? w1 : w2;
    g_wh[idx] = __float2half(w[e]);
}

// Fold outW_t and fcW:  M[c2][t*256+j] = sum_c fcW[c2][t*128+c] * outW_t[c][j]
__global__ void build_M_kernel(const float* __restrict__ fcW,
                               const float* __restrict__ outW_v,
                               const float* __restrict__ outW_h,
                               const float* __restrict__ outW_d) {
    int idx = blockIdx.x * 256 + threadIdx.x;      // 0 .. 128*768-1
    if (idx >= 128 * 768) return;
    int c2 = idx / 768;
    int tj = idx - c2 * 768;
    int t  = tj >> 8;
    int j  = tj & 255;
    const float* oW = (t == 0) ? outW_v : (t == 1) ? outW_h : outW_d;
    const float* fr = fcW + c2 * 384 + t * 128;
    float acc = 0.f;
    #pragma unroll 8
    for (int c = 0; c < 128; c++)
        acc += fr[c] * oW[c * 256 + j];
    g_Mh[idx] = __float2half(acc);
}

// out[m][c] += fcb[c]   (out is (32768,128) fp32)
__global__ void bias_add_kernel(float* __restrict__ out, const float* __restrict__ fcb) {
    int idx = blockIdx.x * 256 + threadIdx.x;      // float4 index, total 1M
    int c4 = idx & 31;                             // 32 float4 per row
    float4 v = ((float4*)out)[idx];
    float4 b = ((const float4*)fcb)[c4];
    v.x += b.x; v.y += b.y; v.z += b.z; v.w += b.w;
    ((float4*)out)[idx] = v;
}

// ---------------------------------------------------------------------------
// Fused depthwise-conv + SiLU + x-proj + dt-proj + selective scan + gating.
// One CTA per sequence (1024 CTAs), 256 threads = one per d_inner channel.
// pos(l) = (blk>>5)*sHi + (blk&31)*sLo + l*sL
// ---------------------------------------------------------------------------
__device__ __forceinline__ float silu_f(float x) {
    return x / (1.f + __expf(-x));
}

__global__ void __launch_bounds__(256)
mamba_scan_kernel(const float* __restrict__ convw,  // (256,4)
                  const float* __restrict__ convb,  // (256)
                  const float* __restrict__ xpW,    // (40,256)
                  const float* __restrict__ dtW,    // (256,8)
                  const float* __restrict__ dtb,    // (256)
                  const float* __restrict__ Alog,   // (256,16)
                  const float* __restrict__ Dp,     // (256)
                  int sHi, int sLo, int sL, int branch) {
    __shared__ float xc_s[LSEQ][DIN];        // 32 KB
    __shared__ float dbc_s[LSEQ][40];        // 5 KB
    __shared__ float xpw_s[40][68];          // 10.6 KB

    const int i   = threadIdx.x;             // channel
    const int blk = blockIdx.x;
    const int base = (blk >> 5) * sHi + (blk & 31) * sLo;

    // ---- Phase 1: depthwise causal conv (width 4) + SiLU -> xc_s ----
    {
        const float cw0 = convw[i * 4 + 0];
        const float cw1 = convw[i * 4 + 1];
        const float cw2 = convw[i * 4 + 2];
        const float cw3 = convw[i * 4 + 3];
        const float cb  = convb[i];
        float w0 = 0.f, w1 = 0.f, w2 = 0.f;
        #pragma unroll
        for (int l = 0; l < LSEQ; l++) {
            float cur = g_xz[(size_t)(base + l * sL) * 512 + i];
            float v = cb + cw0 * w0 + cw1 * w1 + cw2 * w2 + cw3 * cur;
            xc_s[l][i] = silu_f(v);
            w0 = w1; w1 = w2; w2 = cur;
        }
    }
    __syncthreads();

    // ---- Phase 2: dbc[l][j] = xc_s[l][:] . xpW[j][:] ----
    {
        const int l2 = i >> 3;     // 0..31
        const int jg = i & 7;      // 0..7 -> j base jg*5
        float acc5[5] = {0.f, 0.f, 0.f, 0.f, 0.f};

        for (int c = 0; c < 4; c++) {            // K chunks of 64
            for (int e = i; e < 40 * 64; e += 256) {
                int j  = e >> 6;
                int ii = e & 63;
                xpw_s[j][ii] = xpW[j * 256 + c * 64 + ii];
            }
            __syncthreads();
            const float* xr = &xc_s[l2][c * 64];
            #pragma unroll 4
            for (int ii = 0; ii < 64; ii += 4) {
                float4 xv = *(const float4*)(xr + ii);
                #pragma unroll
                for (int p5 = 0; p5 < 5; p5++) {
                    float4 wv = *(const float4*)&xpw_s[jg * 5 + p5][ii];
                    acc5[p5] += xv.x * wv.x + xv.y * wv.y + xv.z * wv.z + xv.w * wv.w;
                }
            }
            __syncthreads();
        }
        #pragma unroll
        for (int p5 = 0; p5 < 5; p5++)
            dbc_s[l2][jg * 5 + p5] = acc5[p5];
    }
    __syncthreads();

    // ---- Phase 3: dt softplus + selective scan + gating ----
    {
        float Areg[NSTATE];
        #pragma unroll
        for (int n = 0; n < NSTATE; n++)
            Areg[n] = -expf(Alog[i * NSTATE + n]);

        // Structural check: A_n == (n+1)*A_0 (standard Mamba init) -> one exp/step
        bool geom = true;
        #pragma unroll
        for (int n = 0; n < NSTATE; n++)
            geom = geom && (fabsf(Areg[n] - (float)(n + 1) * Areg[0])
                            <= 1e-5f * fabsf(Areg[n]));

        float dtw[DTRANK];
        #pragma unroll
        for (int r = 0; r < DTRANK; r++) dtw[r] = dtW[i * DTRANK + r];
        const float dtbi = dtb[i];
        const float dpi  = Dp[i];

        float h[NSTATE];
        #pragma unroll
        for (int n = 0; n < NSTATE; n++) h[n] = 0.f;

        for (int l = 0; l < LSEQ; l++) {
            const size_t pos = (size_t)(base + l * sL);
            float dtv = dtbi;
            #pragma unroll
            for (int r = 0; r < DTRANK; r++) dtv += dbc_s[l][r] * dtw[r];
            dtv = (dtv > 20.f) ? dtv : __logf(1.f + __expf(dtv));

            const float u  = xc_s[l][i];
            const float du = dtv * u;
            float y = 0.f;
            if (geom) {
                const float e1 = __expf(dtv * Areg[0]);
                float p = 1.f;
                #pragma unroll
                for (int n = 0; n < NSTATE; n++) {
                    p *= e1;                                     // e1^(n+1)
                    h[n] = p * h[n] + du * dbc_s[l][DTRANK + n];
                    y += h[n] * dbc_s[l][DTRANK + NSTATE + n];
                }
            } else {
                #pragma unroll
                for (int n = 0; n < NSTATE; n++) {
                    float dA = __expf(dtv * Areg[n]);
                    h[n] = dA * h[n] + du * dbc_s[l][DTRANK + n];
                    y += h[n] * dbc_s[l][DTRANK + NSTATE + n];
                }
            }
            const float z  = g_xz[pos * 512 + 256 + i];
            const float yo = (y + u * dpi) * silu_f(z);
            g_yh[pos * 768 + branch * 256 + i] = __float2half(yo);
        }
    }
}

// ---------------------------------------------------------------------------
// Host launcher
// ---------------------------------------------------------------------------
extern "C" void kernel_launch(void* const* d_in, const int* in_sizes, int n_in,
                              void* d_out, int out_size) {
    (void)in_sizes; (void)n_in; (void)out_size;

    const float* x   = (const float*)d_in[0];
    const float* prm[3][9];
    for (int t = 0; t < 3; t++)
        for (int k = 0; k < 9; k++)
            prm[t][k] = (const float*)d_in[1 + t * 9 + k];
    const float* fcW = (const float*)d_in[28];
    const float* fcb = (const float*)d_in[29];
    float* out = (float*)d_out;

    __half *xh, *wh, *yh, *Mh;
    float *xz;
    cudaGetSymbolAddress((void**)&xh, g_xh);
    cudaGetSymbolAddress((void**)&wh, g_wh);
    cudaGetSymbolAddress((void**)&xz, g_xz);
    cudaGetSymbolAddress((void**)&yh, g_yh);
    cudaGetSymbolAddress((void**)&Mh, g_Mh);

    // Conversions + folded output matrix
    cvt_x_kernel<<<(NPOS * 128 / 4) / 256, 256>>>(x, xh);
    cvt_w_kernel<<<(3 * 65536) / 256, 256>>>(prm[0][0], prm[1][0], prm[2][0]);
    build_M_kernel<<<(128 * 768 + 255) / 256, 256>>>(fcW, prm[0][8], prm[1][8], prm[2][8]);

    // Per-branch sequence strides:  pos = (blk>>5)*sHi + (blk&31)*sLo + l*sL
    const int sHi[3] = {  32, 1024, 1024};
    const int sLo[3] = {   1,    1,   32};
    const int sL [3] = {1024,   32,    1};

    dim3 g1(512 / 128, NPOS / 128);   // in-proj: N=512
    for (int t = 0; t < 3; t++) {
        hgemm_wmma<<<g1, 256>>>(xh, wh + t * 512 * 128, xz, NPOS, 512, 128);
        mamba_scan_kernel<<<1024, 256>>>(prm[t][1], prm[t][2], prm[t][3], prm[t][4],
                                         prm[t][5], prm[t][6], prm[t][7],
                                         sHi[t], sLo[t], sL[t], t);
    }

    // out = ybuf(32768,768) @ M(128,768)^T, then +fcb
    dim3 g2(1, NPOS / 128);
    hgemm_wmma<<<g2, 256>>>(yh, Mh, out, NPOS, 128, 768);
    bias_add_kernel<<<(NPOS * 128 / 4) / 256, 256>>>(out, fcb);
}

// round 8
// speedup vs baseline: 2.3414x; 1.2525x over previous
#include <cuda_runtime.h>
#include <cuda_fp16.h>
#include <mma.h>
#include <cstdint>
#include <cstddef>

using namespace nvcuda;

// ---------------------------------------------------------------------------
// Problem constants
// ---------------------------------------------------------------------------
#define NPOS   32768          // B*H*W*D = 1*32*32*32
#define CMODEL 128
#define DIN    256
#define NSTATE 16
#define DTRANK 8
#define LSEQ   32

// Scratch (device globals; no allocation allowed)
__device__ __half g_xh [(size_t)NPOS * 128];   // x in fp16 (in-proj A operand)
__device__ __half g_wh [3 * 512 * 128];        // inW per branch, fp16 (N=512, K=128)
__device__ float  g_xz [(size_t)NPOS * 512];   // in-projection output (xi | z), fp32
__device__ __half g_xch[(size_t)NPOS * 256];   // conv+silu output xc, fp16 (per branch reuse)
__device__ float  g_P  [(size_t)NPOS * 128];   // x-proj output dbc (cols 0..39), fp32
__device__ __half g_w2h[3 * 128 * 256];        // xpW padded to 128 rows, fp16, per branch
__device__ __half g_yh [(size_t)NPOS * 768];   // pre-out-proj y (3 branches), fp16
__device__ __half g_Mh [128 * 768];            // folded (outW_t -> fcW), fp16 (N=128,K=768)

// ===========================================================================
// WMMA fp16 GEMM: C[M,N](fp32) = A[M,K](fp16) @ B[N,K](fp16)^T
// BM=BN=128, BK=64, 256 threads (8 warps, each 64x32).
// Requires M%128==0, N%128==0, K%64==0.
// ===========================================================================
__global__ void __launch_bounds__(256)
hgemm_wmma(const __half* __restrict__ A, const __half* __restrict__ B,
           float* __restrict__ C, int M, int N, int K) {
    __shared__ __half As[128][72];     // 64 + 8 pad
    __shared__ __half Bs[128][72];

    const int tid = threadIdx.x;
    const int wid = tid >> 5;
    const int warp_m = wid & 1;        // 0..1 -> 64-row slab
    const int warp_n = wid >> 1;       // 0..3 -> 32-col slab
    const int bm = blockIdx.y * 128;
    const int bn = blockIdx.x * 128;

    wmma::fragment<wmma::accumulator, 16, 16, 16, float> acc[4][2];
    #pragma unroll
    for (int i = 0; i < 4; i++)
        #pragma unroll
        for (int j = 0; j < 2; j++)
            wmma::fill_fragment(acc[i][j], 0.f);

    for (int k0 = 0; k0 < K; k0 += 64) {
        #pragma unroll
        for (int it = 0; it < 4; it++) {
            int idx = tid + it * 256;          // 0..1023
            int r = idx >> 3, c8 = idx & 7;    // row, 8-half group
            const uint4* Ag = (const uint4*)(A + (size_t)(bm + r) * K + k0);
            *(uint4*)&As[r][c8 * 8] = Ag[c8];
            const uint4* Bg = (const uint4*)(B + (size_t)(bn + r) * K + k0);
            *(uint4*)&Bs[r][c8 * 8] = Bg[c8];
        }
        __syncthreads();

        #pragma unroll
        for (int kk = 0; kk < 64; kk += 16) {
            wmma::fragment<wmma::matrix_a, 16, 16, 16, __half, wmma::row_major> af[4];
            wmma::fragment<wmma::matrix_b, 16, 16, 16, __half, wmma::col_major> bf[2];
            #pragma unroll
            for (int i = 0; i < 4; i++)
                wmma::load_matrix_sync(af[i], &As[warp_m * 64 + i * 16][kk], 72);
            #pragma unroll
            for (int j = 0; j < 2; j++)
                wmma::load_matrix_sync(bf[j], &Bs[warp_n * 32 + j * 16][kk], 72);
            #pragma unroll
            for (int i = 0; i < 4; i++)
                #pragma unroll
                for (int j = 0; j < 2; j++)
                    wmma::mma_sync(acc[i][j], af[i], bf[j], acc[i][j]);
        }
        __syncthreads();
    }

    #pragma unroll
    for (int i = 0; i < 4; i++)
        #pragma unroll
        for (int j = 0; j < 2; j++) {
            int row = bm + warp_m * 64 + i * 16;
            int col = bn + warp_n * 32 + j * 16;
            wmma::store_matrix_sync(C + (size_t)row * N + col, acc[i][j], N,
                                    wmma::mem_row_major);
        }
}

// ---------------------------------------------------------------------------
// Conversion / setup kernels
// ---------------------------------------------------------------------------
__global__ void cvt_x_kernel(const float* __restrict__ x, __half* __restrict__ xh) {
    int idx = blockIdx.x * 256 + threadIdx.x;       // float4 index, total 1M
    float4 v = ((const float4*)x)[idx];
    __half2 a = __floats2half2_rn(v.x, v.y);
    __half2 b = __floats2half2_rn(v.z, v.w);
    uint2 o;
    o.x = *(uint32_t*)&a;
    o.y = *(uint32_t*)&b;
    ((uint2*)xh)[idx] = o;
}

__global__ void cvt_w_kernel(const float* __restrict__ w0, const float* __restrict__ w1,
                             const float* __restrict__ w2) {
    int idx = blockIdx.x * 256 + threadIdx.x;       // 0 .. 3*65536-1
    int t = idx >> 16;
    int e = idx & 65535;
    const float* w = (t == 0) ? w0 : (t == 1) ? w1 : w2;
    g_wh[idx] = __float2half(w[e]);
}

// xpW (40,256) -> fp16, padded to 128 rows, per branch
__global__ void build_W2_kernel(const float* __restrict__ xp0, const float* __restrict__ xp1,
                                const float* __restrict__ xp2) {
    int idx = blockIdx.x * 256 + threadIdx.x;       // 0 .. 3*32768-1
    int t = idx >> 15;
    int e = idx & 32767;
    int row = e >> 8;
    int k = e & 255;
    const float* xp = (t == 0) ? xp0 : (t == 1) ? xp1 : xp2;
    float v = (row < 40) ? xp[row * 256 + k] : 0.f;
    g_w2h[idx] = __float2half(v);
}

// Fold outW_t and fcW:  M[c2][t*256+j] = sum_c fcW[c2][t*128+c] * outW_t[c][j]
__global__ void build_M_kernel(const float* __restrict__ fcW,
                               const float* __restrict__ outW_v,
                               const float* __restrict__ outW_h,
                               const float* __restrict__ outW_d) {
    int idx = blockIdx.x * 256 + threadIdx.x;      // 0 .. 128*768-1
    if (idx >= 128 * 768) return;
    int c2 = idx / 768;
    int tj = idx - c2 * 768;
    int t  = tj >> 8;
    int j  = tj & 255;
    const float* oW = (t == 0) ? outW_v : (t == 1) ? outW_h : outW_d;
    const float* fr = fcW + c2 * 384 + t * 128;
    float acc = 0.f;
    #pragma unroll 8
    for (int c = 0; c < 128; c++)
        acc += fr[c] * oW[c * 256 + j];
    g_Mh[idx] = __float2half(acc);
}

// out[m][c] += fcb[c]   (out is (32768,128) fp32)
__global__ void bias_add_kernel(float* __restrict__ out, const float* __restrict__ fcb) {
    int idx = blockIdx.x * 256 + threadIdx.x;      // float4 index, total 1M
    int c4 = idx & 31;                             // 32 float4 per row
    float4 v = ((float4*)out)[idx];
    float4 b = ((const float4*)fcb)[c4];
    v.x += b.x; v.y += b.y; v.z += b.z; v.w += b.w;
    ((float4*)out)[idx] = v;
}

// ---------------------------------------------------------------------------
// Depthwise causal conv (width 4) + SiLU -> g_xch (fp16)
// grid 1024 (sequences), block 256 (channels). Running window in registers.
// pos(l) = (blk>>5)*sHi + (blk&31)*sLo + l*sL
// ---------------------------------------------------------------------------
__device__ __forceinline__ float silu_f(float x) {
    return x / (1.f + __expf(-x));
}

__global__ void __launch_bounds__(256)
conv_silu_kernel(const float* __restrict__ convw,  // (256,4)
                 const float* __restrict__ convb,  // (256)
                 int sHi, int sLo, int sL) {
    const int i   = threadIdx.x;
    const int blk = blockIdx.x;
    const int base = (blk >> 5) * sHi + (blk & 31) * sLo;

    const float cw0 = convw[i * 4 + 0];
    const float cw1 = convw[i * 4 + 1];
    const float cw2 = convw[i * 4 + 2];
    const float cw3 = convw[i * 4 + 3];
    const float cb  = convb[i];
    float w0 = 0.f, w1 = 0.f, w2 = 0.f;
    #pragma unroll
    for (int l = 0; l < LSEQ; l++) {
        const size_t pos = (size_t)(base + l * sL);
        float cur = g_xz[pos * 512 + i];
        float v = cb + cw0 * w0 + cw1 * w1 + cw2 * w2 + cw3 * cur;
        g_xch[pos * 256 + i] = __float2half(silu_f(v));
        w0 = w1; w1 = w2; w2 = cur;
    }
}

// ---------------------------------------------------------------------------
// Lean selective scan: dt-proj (fp32) + softplus + recurrence + gating.
// Reads dbc from g_P (cols 0..39), u from g_xch, z from g_xz.
// grid 1024, block 256, smem ~5.1KB -> high occupancy.
// ---------------------------------------------------------------------------
__global__ void __launch_bounds__(256)
mamba_scan2_kernel(const float* __restrict__ dtW,   // (256,8)
                   const float* __restrict__ dtb,   // (256)
                   const float* __restrict__ Alog,  // (256,16)
                   const float* __restrict__ Dp,    // (256)
                   int sHi, int sLo, int sL, int branch) {
    __shared__ float dbc_s[LSEQ][40];

    const int i   = threadIdx.x;
    const int blk = blockIdx.x;
    const int base = (blk >> 5) * sHi + (blk & 31) * sLo;

    // Stage dbc rows for this sequence: 32 x 40 floats
    for (int idx = i; idx < LSEQ * 40; idx += 256) {
        int l = idx / 40;
        int j = idx - l * 40;
        const size_t pos = (size_t)(base + l * sL);
        dbc_s[l][j] = g_P[pos * 128 + j];
    }
    __syncthreads();

    float Areg[NSTATE];
    #pragma unroll
    for (int n = 0; n < NSTATE; n++)
        Areg[n] = -expf(Alog[i * NSTATE + n]);

    // Structural check: A_n == (n+1)*A_0 (standard Mamba init) -> one exp/step
    bool geom = true;
    #pragma unroll
    for (int n = 0; n < NSTATE; n++)
        geom = geom && (fabsf(Areg[n] - (float)(n + 1) * Areg[0])
                        <= 1e-5f * fabsf(Areg[n]));

    float dtw[DTRANK];
    #pragma unroll
    for (int r = 0; r < DTRANK; r++) dtw[r] = dtW[i * DTRANK + r];
    const float dtbi = dtb[i];
    const float dpi  = Dp[i];

    float h[NSTATE];
    #pragma unroll
    for (int n = 0; n < NSTATE; n++) h[n] = 0.f;

    for (int l = 0; l < LSEQ; l++) {
        const size_t pos = (size_t)(base + l * sL);
        float dtv = dtbi;
        #pragma unroll
        for (int r = 0; r < DTRANK; r++) dtv += dbc_s[l][r] * dtw[r];
        dtv = (dtv > 20.f) ? dtv : __logf(1.f + __expf(dtv));

        const float u  = __half2float(g_xch[pos * 256 + i]);
        const float du = dtv * u;
        float y = 0.f;
        if (geom) {
            const float e1 = __expf(dtv * Areg[0]);
            float p = 1.f;
            #pragma unroll
            for (int n = 0; n < NSTATE; n++) {
                p *= e1;                                     // e1^(n+1)
                h[n] = p * h[n] + du * dbc_s[l][DTRANK + n];
                y += h[n] * dbc_s[l][DTRANK + NSTATE + n];
            }
        } else {
            #pragma unroll
            for (int n = 0; n < NSTATE; n++) {
                float dA = __expf(dtv * Areg[n]);
                h[n] = dA * h[n] + du * dbc_s[l][DTRANK + n];
                y += h[n] * dbc_s[l][DTRANK + NSTATE + n];
            }
        }
        const float z  = g_xz[pos * 512 + 256 + i];
        const float yo = (y + u * dpi) * silu_f(z);
        g_yh[pos * 768 + branch * 256 + i] = __float2half(yo);
    }
}

// ---------------------------------------------------------------------------
// Host launcher
// ---------------------------------------------------------------------------
extern "C" void kernel_launch(void* const* d_in, const int* in_sizes, int n_in,
                              void* d_out, int out_size) {
    (void)in_sizes; (void)n_in; (void)out_size;

    const float* x   = (const float*)d_in[0];
    const float* prm[3][9];
    for (int t = 0; t < 3; t++)
        for (int k = 0; k < 9; k++)
            prm[t][k] = (const float*)d_in[1 + t * 9 + k];
    const float* fcW = (const float*)d_in[28];
    const float* fcb = (const float*)d_in[29];
    float* out = (float*)d_out;

    __half *xh, *wh, *xch, *w2h, *yh, *Mh;
    float *xz, *P;
    cudaGetSymbolAddress((void**)&xh,  g_xh);
    cudaGetSymbolAddress((void**)&wh,  g_wh);
    cudaGetSymbolAddress((void**)&xz,  g_xz);
    cudaGetSymbolAddress((void**)&xch, g_xch);
    cudaGetSymbolAddress((void**)&P,   g_P);
    cudaGetSymbolAddress((void**)&w2h, g_w2h);
    cudaGetSymbolAddress((void**)&yh,  g_yh);
    cudaGetSymbolAddress((void**)&Mh,  g_Mh);

    // Conversions + weight folds
    cvt_x_kernel<<<(NPOS * 128 / 4) / 256, 256>>>(x, xh);
    cvt_w_kernel<<<(3 * 65536) / 256, 256>>>(prm[0][0], prm[1][0], prm[2][0]);
    build_W2_kernel<<<(3 * 32768) / 256, 256>>>(prm[0][3], prm[1][3], prm[2][3]);
    build_M_kernel<<<(128 * 768 + 255) / 256, 256>>>(fcW, prm[0][8], prm[1][8], prm[2][8]);

    // Per-branch sequence strides:  pos = (blk>>5)*sHi + (blk&31)*sLo + l*sL
    const int sHi[3] = {  32, 1024, 1024};
    const int sLo[3] = {   1,    1,   32};
    const int sL [3] = {1024,   32,    1};

    dim3 g1(512 / 128, NPOS / 128);   // in-proj: N=512
    dim3 gp(1, NPOS / 128);           // x-proj: N=128
    for (int t = 0; t < 3; t++) {
        // xz = x @ inW_t^T
        hgemm_wmma<<<g1, 256>>>(xh, wh + t * 512 * 128, xz, NPOS, 512, 128);
        // xc = silu(causal_conv(xi))
        conv_silu_kernel<<<1024, 256>>>(prm[t][1], prm[t][2], sHi[t], sLo[t], sL[t]);
        // dbc = xc @ xpW^T (padded to 128 cols)
        hgemm_wmma<<<gp, 256>>>(xch, w2h + t * 128 * 256, P, NPOS, 128, 256);
        // recurrence
        mamba_scan2_kernel<<<1024, 256>>>(prm[t][4], prm[t][5], prm[t][6], prm[t][7],
                                          sHi[t], sLo[t], sL[t], t);
    }

    // out = ybuf(32768,768) @ M(128,768)^T, then +fcb
    dim3 g2(1, NPOS / 128);
    hgemm_wmma<<<g2, 256>>>(yh, Mh, out, NPOS, 128, 768);
    bias_add_kernel<<<(NPOS * 128 / 4) / 256, 256>>>(out, fcb);
}